// round 6
// baseline (speedup 1.0000x reference)
#include <cuda_runtime.h>
#include <stdint.h>

#define THREADS 512
#define NBINS   2048
#define BSHIFT  21
#define CAP     512      // candidate list capacity per side
#define TCAP    128      // boundary-bin list capacity
#define FDIM    8192
#define EPT     16
#define VPT     4

__device__ __forceinline__ unsigned f2key(float f) {
    unsigned u = __float_as_uint(f);
    return u ^ ((unsigned)((int)u >> 31) | 0x80000000u);
}
__device__ __forceinline__ float key2f(unsigned k) {
    unsigned m = (~(unsigned)((int)k >> 31)) | 0x80000000u;
    return __uint_as_float(k ^ m);
}

__global__ __launch_bounds__(THREADS, 2)
void topk_mask_kernel(const float* __restrict__ x, const float* __restrict__ w,
                      const int* __restrict__ kp, float* __restrict__ out)
{
    __shared__ __align__(16) unsigned hist[NBINS];   // sample hist
    __shared__ __align__(16) unsigned histC[NBINS];  // candidate hist
    __shared__ unsigned part[THREADS];
    __shared__ unsigned listKH[CAP], listIH[CAP], listKL[CAP], listIL[CAP];
    __shared__ unsigned tKH[TCAP], tIH[TCAP], tKL[TCAP], tIL[TCAP];
    __shared__ int s_cntH, s_cntL, s_mH, s_mL;
    __shared__ unsigned s_EH, s_EL;                  // loose edge compare keys
    __shared__ int s_Bh, s_Bl, s_rh, s_rl;
    __shared__ unsigned s_Th, s_Ih, s_Tl, s_Il;
    __shared__ int s_red;
    __shared__ int s_K;

    const int tid  = threadIdx.x;
    const int lane = tid & 31;
    const int warp = tid >> 5;
    const int b    = blockIdx.x;

    if (tid == 0) {
        s_cntH = 0; s_cntL = 0; s_mH = 0; s_mL = 0;
        s_Bh = -1; s_Bl = -1;
        s_K = kp ? kp[0] : 64;
    }
    ((uint4*)hist)[tid]  = make_uint4(0,0,0,0);
    ((uint4*)histC)[tid] = make_uint4(0,0,0,0);
    __syncthreads();
    const int K = s_K;
    int sr = (2 * K * 1024) / FDIM + 8;
    if (sr > 1024) sr = 1024;
    if (sr < 1)    sr = 1;
    const int SRANK = sr;

    const float4* xr = (const float4*)(x + (size_t)b * FDIM);
    const float4* wr = (const float4*)w;
    float4* orow     = (float4*)(out + (size_t)b * FDIM);

    // ---- P1: load, multiply, keys in registers; 2 sample atomics ----
    unsigned key[EPT];
    #pragma unroll
    for (int k = 0; k < VPT; k++) {
        int v = tid + k * THREADS;
        float4 xv = xr[v];
        float4 wv = wr[v];
        key[4*k+0] = f2key(xv.x * wv.x);
        key[4*k+1] = f2key(xv.y * wv.y);
        key[4*k+2] = f2key(xv.z * wv.z);
        key[4*k+3] = f2key(xv.w * wv.w);
    }
    atomicAdd(&hist[key[0] >> BSHIFT], 1u);
    atomicAdd(&hist[key[8] >> BSHIFT], 1u);
    __syncthreads();

    // ---- P2: sample resolve -> loose edges (as key-compare values) ----
    {
        uint4 a = ((const uint4*)hist)[tid];
        part[tid] = a.x + a.y + a.z + a.w;
    }
    __syncthreads();
    if (warp == 0) {
        unsigned g = 0;
        #pragma unroll
        for (int p = 0; p < 16; p++) g += part[lane*16 + p];
        unsigned acc = g;
        #pragma unroll
        for (int off = 1; off < 32; off <<= 1) {
            unsigned vv = __shfl_down_sync(0xFFFFFFFFu, acc, off);
            if (lane + off < 32) acc += vv;
        }
        unsigned above = acc - g;
        if ((int)above < SRANK && (int)(above + g) >= SRANK) {
            unsigned run = above;
            int base = lane * 16;
            for (int p = 15; p >= 0; --p) {
                unsigned pc = part[base + p];
                if ((int)(run + pc) >= SRANK) {
                    int bb = (base + p) * 4;
                    for (int b4 = 3; b4 >= 0; --b4) {
                        unsigned c = hist[bb + b4];
                        if ((int)(run + c) >= SRANK) { s_EH = (unsigned)(bb + b4) << BSHIFT; break; }
                        run += c;
                    }
                    break;
                }
                run += pc;
            }
        }
    } else if (warp == 1) {
        unsigned g = 0;
        #pragma unroll
        for (int p = 0; p < 16; p++) g += part[lane*16 + p];
        unsigned acc = g;
        #pragma unroll
        for (int off = 1; off < 32; off <<= 1) {
            unsigned vv = __shfl_up_sync(0xFFFFFFFFu, acc, off);
            if (lane >= off) acc += vv;
        }
        unsigned below = acc - g;
        if ((int)below < SRANK && (int)(below + g) >= SRANK) {
            unsigned run = below;
            int base = lane * 16;
            for (int p = 0; p < 16; ++p) {
                unsigned pc = part[base + p];
                if ((int)(run + pc) >= SRANK) {
                    int bb = (base + p) * 4;
                    for (int b4 = 0; b4 < 4; ++b4) {
                        unsigned c = hist[bb + b4];
                        if ((int)(run + c) >= SRANK) {
                            s_EL = ((unsigned)(bb + b4) << BSHIFT) | ((1u << BSHIFT) - 1u);
                            break;
                        }
                        run += c;
                    }
                    break;
                }
                run += pc;
            }
        }
    }
    __syncthreads();

    // ---- P3: ballot-aggregated candidate append (both sides, one sweep) ----
    {
        const unsigned EH = s_EH, EL = s_EL;
        const unsigned ltmask = (1u << lane) - 1u;
        #pragma unroll
        for (int e = 0; e < EPT; e++) {
            unsigned kk  = key[e];
            unsigned idx = (unsigned)(4*(tid + (e>>2)*THREADS) + (e&3));
            bool hi = kk >= EH;
            unsigned mh = __ballot_sync(0xFFFFFFFFu, hi);
            if (mh) {
                int ldr = __ffs(mh) - 1;
                int base = 0;
                if (lane == ldr) base = atomicAdd(&s_cntH, __popc(mh));
                base = __shfl_sync(0xFFFFFFFFu, base, ldr);
                if (hi) {
                    int p = base + __popc(mh & ltmask);
                    if (p < CAP) { listKH[p] = kk; listIH[p] = idx; }
                }
            }
            bool lo = kk <= EL;
            unsigned ml = __ballot_sync(0xFFFFFFFFu, lo);
            if (ml) {
                int ldr = __ffs(ml) - 1;
                int base = 0;
                if (lane == ldr) base = atomicAdd(&s_cntL, __popc(ml));
                base = __shfl_sync(0xFFFFFFFFu, base, ldr);
                if (lo) {
                    int p = base + __popc(ml & ltmask);
                    if (p < CAP) { listKL[p] = kk; listIL[p] = idx; }
                }
            }
        }
    }
    __syncthreads();

    const int nH = s_cntH, nL = s_cntL;
    bool fbH = (nH < K) || (nH > CAP);
    bool fbL = (nL < K) || (nL > CAP);

    // ---- P4: mini-histogram over candidate lists ----
    if (!fbH && tid < nH) atomicAdd(&histC[listKH[tid] >> BSHIFT], 1u);
    if (!fbL && tid < nL) atomicAdd(&histC[listKL[tid] >> BSHIFT], 1u);
    __syncthreads();

    // ---- P5: exact rank-K resolve over candidate histogram ----
    {
        uint4 a = ((const uint4*)histC)[tid];
        part[tid] = a.x + a.y + a.z + a.w;
    }
    __syncthreads();
    if (warp == 0 && !fbH) {
        unsigned g = 0;
        #pragma unroll
        for (int p = 0; p < 16; p++) g += part[lane*16 + p];
        unsigned acc = g;
        #pragma unroll
        for (int off = 1; off < 32; off <<= 1) {
            unsigned vv = __shfl_down_sync(0xFFFFFFFFu, acc, off);
            if (lane + off < 32) acc += vv;
        }
        unsigned above = acc - g;
        if ((int)above < K && (int)(above + g) >= K) {
            unsigned run = above;
            int base = lane * 16;
            for (int p = 15; p >= 0; --p) {
                unsigned pc = part[base + p];
                if ((int)(run + pc) >= K) {
                    int bb = (base + p) * 4;
                    for (int b4 = 3; b4 >= 0; --b4) {
                        unsigned c = histC[bb + b4];
                        if ((int)(run + c) >= K) { s_Bh = bb + b4; s_rh = K - (int)run; break; }
                        run += c;
                    }
                    break;
                }
                run += pc;
            }
        }
    } else if (warp == 1 && !fbL) {
        unsigned g = 0;
        #pragma unroll
        for (int p = 0; p < 16; p++) g += part[lane*16 + p];
        unsigned acc = g;
        #pragma unroll
        for (int off = 1; off < 32; off <<= 1) {
            unsigned vv = __shfl_up_sync(0xFFFFFFFFu, acc, off);
            if (lane >= off) acc += vv;
        }
        unsigned below = acc - g;
        if ((int)below < K && (int)(below + g) >= K) {
            unsigned run = below;
            int base = lane * 16;
            for (int p = 0; p < 16; ++p) {
                unsigned pc = part[base + p];
                if ((int)(run + pc) >= K) {
                    int bb = (base + p) * 4;
                    for (int b4 = 0; b4 < 4; ++b4) {
                        unsigned c = histC[bb + b4];
                        if ((int)(run + c) >= K) { s_Bl = bb + b4; s_rl = K - (int)run; break; }
                        run += c;
                    }
                    break;
                }
                run += pc;
            }
        }
    }
    __syncthreads();
    fbH = fbH || (s_Bh < 0);
    fbL = fbL || (s_Bl < 0);

    // ---- P6: boundary-bin gather (from candidate lists) ----
    if (!fbH && tid < nH) {
        unsigned kk = listKH[tid];
        if ((int)(kk >> BSHIFT) == s_Bh) {
            int p = atomicAdd(&s_mH, 1);
            if (p < TCAP) { tKH[p] = kk; tIH[p] = listIH[tid]; }
        }
    }
    if (!fbL && tid < nL) {
        unsigned kk = listKL[tid];
        if ((int)(kk >> BSHIFT) == s_Bl) {
            int p = atomicAdd(&s_mL, 1);
            if (p < TCAP) { tKL[p] = kk; tIL[p] = listIL[tid]; }
        }
    }
    __syncthreads();
    const int mH = s_mH, mL = s_mL;
    fbH = fbH || (mH > TCAP);
    fbL = fbL || (mL > TCAP);

    // ---- P7: tiny O(m^2) tie-exact resolve ----
    if (!fbH && tid < mH) {
        unsigned kj = tKH[tid], ij = tIH[tid];
        int rank = 0;
        for (int i = 0; i < mH; i++) {
            unsigned ki = tKH[i], ii = tIH[i];
            rank += (ki > kj) || (ki == kj && ii < ij);
        }
        if (rank == s_rh - 1) { s_Th = kj; s_Ih = ij; }
    }
    if (!fbL && tid < mL) {
        unsigned kj = tKL[tid], ij = tIL[tid];
        int rank = 0;
        for (int i = 0; i < mL; i++) {
            unsigned ki = tKL[i], ii = tIL[i];
            rank += (ki < kj) || (ki == kj && ii < ij);
        }
        if (rank == s_rl - 1) { s_Tl = kj; s_Il = ij; }
    }

    // ---- P8: rare exact fallback (binary search over register keys) ----
    if (fbH) {
        unsigned lo = 0, hi = 0xFFFFFFFFu;
        for (int it = 0; it < 32; ++it) {
            unsigned mid = lo + ((hi - lo) >> 1);
            if (tid == 0) s_red = 0;
            __syncthreads();
            int c = 0;
            #pragma unroll
            for (int e = 0; e < EPT; e++) c += (key[e] > mid);
            c = __reduce_add_sync(0xFFFFFFFFu, c);
            if (lane == 0) atomicAdd(&s_red, c);
            __syncthreads();
            int tot = s_red; __syncthreads();
            if (tot >= K) lo = mid + 1; else hi = mid;
        }
        unsigned Th = lo;
        if (tid == 0) s_red = 0;
        __syncthreads();
        { int c = 0;
          #pragma unroll
          for (int e = 0; e < EPT; e++) c += (key[e] > Th);
          c = __reduce_add_sync(0xFFFFFFFFu, c);
          if (lane == 0) atomicAdd(&s_red, c); }
        __syncthreads();
        int r = K - s_red; __syncthreads();
        unsigned lo2 = 0, hi2 = FDIM - 1;
        for (int it = 0; it < 13; ++it) {
            unsigned mid = lo2 + ((hi2 - lo2) >> 1);
            if (tid == 0) s_red = 0;
            __syncthreads();
            int c = 0;
            #pragma unroll
            for (int e = 0; e < EPT; e++) {
                unsigned idx = (unsigned)(4*(tid + (e>>2)*THREADS) + (e&3));
                c += (key[e] == Th && idx <= mid);
            }
            c = __reduce_add_sync(0xFFFFFFFFu, c);
            if (lane == 0) atomicAdd(&s_red, c);
            __syncthreads();
            int tot = s_red; __syncthreads();
            if (tot >= r) hi2 = mid; else lo2 = mid + 1;
        }
        if (tid == 0) { s_Th = Th; s_Ih = lo2; }
    }
    if (fbL) {
        unsigned lo = 0, hi = 0xFFFFFFFFu;
        for (int it = 0; it < 32; ++it) {
            unsigned mid = lo + ((hi - lo) >> 1);
            if (tid == 0) s_red = 0;
            __syncthreads();
            int c = 0;
            #pragma unroll
            for (int e = 0; e < EPT; e++) c += (key[e] <= mid);
            c = __reduce_add_sync(0xFFFFFFFFu, c);
            if (lane == 0) atomicAdd(&s_red, c);
            __syncthreads();
            int tot = s_red; __syncthreads();
            if (tot >= K) hi = mid; else lo = mid + 1;
        }
        unsigned Tl = lo;
        if (tid == 0) s_red = 0;
        __syncthreads();
        { int c = 0;
          #pragma unroll
          for (int e = 0; e < EPT; e++) c += (key[e] < Tl);
          c = __reduce_add_sync(0xFFFFFFFFu, c);
          if (lane == 0) atomicAdd(&s_red, c); }
        __syncthreads();
        int r = K - s_red; __syncthreads();
        unsigned lo2 = 0, hi2 = FDIM - 1;
        for (int it = 0; it < 13; ++it) {
            unsigned mid = lo2 + ((hi2 - lo2) >> 1);
            if (tid == 0) s_red = 0;
            __syncthreads();
            int c = 0;
            #pragma unroll
            for (int e = 0; e < EPT; e++) {
                unsigned idx = (unsigned)(4*(tid + (e>>2)*THREADS) + (e&3));
                c += (key[e] == Tl && idx <= mid);
            }
            c = __reduce_add_sync(0xFFFFFFFFu, c);
            if (lane == 0) atomicAdd(&s_red, c);
            __syncthreads();
            int tot = s_red; __syncthreads();
            if (tot >= r) hi2 = mid; else lo2 = mid + 1;
        }
        if (tid == 0) { s_Tl = Tl; s_Il = lo2; }
    }
    __syncthreads();

    // ---- P9: masked write-out ----
    const unsigned Th = s_Th, Ih = s_Ih, Tl = s_Tl, Il = s_Il;
    #pragma unroll
    for (int k = 0; k < VPT; k++) {
        int v = tid + k * THREADS;
        float vals[4];
        #pragma unroll
        for (int c = 0; c < 4; c++) {
            unsigned kk  = key[4*k + c];
            unsigned idx = (unsigned)(4*v + c);
            bool z = (kk > Th) || (kk < Tl) ||
                     (kk == Th && idx <= Ih) ||
                     (kk == Tl && idx <= Il);
            vals[c] = z ? 0.0f : key2f(kk);
        }
        float4 o; o.x = vals[0]; o.y = vals[1]; o.z = vals[2]; o.w = vals[3];
        orow[v] = o;
    }
}

extern "C" void kernel_launch(void* const* d_in, const int* in_sizes, int n_in,
                              void* d_out, int out_size)
{
    const float* x = (const float*)d_in[0];
    const float* w = (const float*)d_in[1];
    const int* kp  = (n_in >= 3) ? (const int*)d_in[2] : nullptr;

    int Fdim = in_sizes[1];
    int B    = in_sizes[0] / Fdim;

    topk_mask_kernel<<<B, THREADS>>>(x, w, kp, (float*)d_out);
}

// round 7
// speedup vs baseline: 3.2337x; 3.2337x over previous
#include <cuda_runtime.h>
#include <stdint.h>

#define THREADS 512
#define NBINS   2048
#define BSHIFT  21            // key >> 21 -> 2048 bins
#define HCOPY   4             // replicated histogram copies
#define HSTRIDE 2056          // 2048 + 8 words: shifts banks per copy
#define CAP     256
#define FDIM    8192
#define EPT     16
#define VPT     4

// Order-preserving float -> uint32 (ascending)
__device__ __forceinline__ unsigned f2key(float f) {
    unsigned u = __float_as_uint(f);
    return u ^ ((unsigned)((int)u >> 31) | 0x80000000u);
}
// Exact inverse
__device__ __forceinline__ float key2f(unsigned k) {
    unsigned m = (~(unsigned)((int)k >> 31)) | 0x80000000u;
    return __uint_as_float(k ^ m);
}

__global__ __launch_bounds__(THREADS, 2)
void topk_mask_kernel(const float* __restrict__ x, const float* __restrict__ w,
                      const int* __restrict__ kp, float* __restrict__ out)
{
    __shared__ __align__(16) unsigned hist[HCOPY * HSTRIDE];   // ~32.9 KB
    __shared__ unsigned part[THREADS];
    __shared__ unsigned listKH[CAP], listIH[CAP], listKL[CAP], listIL[CAP];
    __shared__ int s_cntH, s_cntL;
    __shared__ int s_Bh, s_Bl, s_rh, s_rl;
    __shared__ unsigned s_Th, s_Ih, s_Tl, s_Il;
    __shared__ int s_red;
    __shared__ int s_K;

    const int tid  = threadIdx.x;
    const int lane = tid & 31;
    const int warp = tid >> 5;
    const int b    = blockIdx.x;

    if (tid == 0) { s_cntH = 0; s_cntL = 0; s_K = kp ? kp[0] : 64; }
    // clear all histogram copies
    for (int i = tid; i < HCOPY * HSTRIDE / 4; i += THREADS)
        ((uint4*)hist)[i] = make_uint4(0,0,0,0);
    __syncthreads();
    const int K = s_K;

    const float4* xr = (const float4*)(x + (size_t)b * FDIM);
    const float4* wr = (const float4*)w;
    float4* orow     = (float4*)(out + (size_t)b * FDIM);

    // ---- Phase 0: load, multiply, key (registers), replicated histogram ----
    unsigned key[EPT];
    unsigned* myhist = hist + (warp & (HCOPY - 1)) * HSTRIDE;
    #pragma unroll
    for (int k = 0; k < VPT; k++) {
        int v = tid + k * THREADS;
        float4 xv = xr[v];
        float4 wv = wr[v];
        key[4*k+0] = f2key(xv.x * wv.x);
        key[4*k+1] = f2key(xv.y * wv.y);
        key[4*k+2] = f2key(xv.z * wv.z);
        key[4*k+3] = f2key(xv.w * wv.w);
        atomicAdd(&myhist[key[4*k+0] >> BSHIFT], 1u);
        atomicAdd(&myhist[key[4*k+1] >> BSHIFT], 1u);
        atomicAdd(&myhist[key[4*k+2] >> BSHIFT], 1u);
        atomicAdd(&myhist[key[4*k+3] >> BSHIFT], 1u);
    }
    __syncthreads();

    // ---- Phase 1a: partial sums, 4 bins per thread (summed over copies) ----
    {
        unsigned s = 0;
        #pragma unroll
        for (int c = 0; c < HCOPY; c++) {
            uint4 a = *(const uint4*)&hist[c * HSTRIDE + tid * 4];
            s += a.x + a.y + a.z + a.w;
        }
        part[tid] = s;
    }
    __syncthreads();

    // ---- Phase 1b: boundary bins. warp0 = top (desc), warp1 = bottom (asc) ----
    if (warp == 0) {
        unsigned g = 0;
        #pragma unroll
        for (int p = 0; p < 16; p++) g += part[lane*16 + p];
        unsigned acc = g;
        #pragma unroll
        for (int off = 1; off < 32; off <<= 1) {
            unsigned vv = __shfl_down_sync(0xFFFFFFFFu, acc, off);
            if (lane + off < 32) acc += vv;
        }
        unsigned above = acc - g;
        if ((int)above < K && (int)(above + g) >= K) {
            unsigned run = above;
            int base = lane * 16;
            for (int p = 15; p >= 0; --p) {
                unsigned pc = part[base + p];
                if ((int)(run + pc) >= K) {
                    int bb = (base + p) * 4;
                    for (int b4 = 3; b4 >= 0; --b4) {
                        unsigned c = hist[bb + b4] + hist[HSTRIDE + bb + b4]
                                   + hist[2*HSTRIDE + bb + b4] + hist[3*HSTRIDE + bb + b4];
                        if ((int)(run + c) >= K) { s_Bh = bb + b4; s_rh = K - (int)run; break; }
                        run += c;
                    }
                    break;
                }
                run += pc;
            }
        }
    } else if (warp == 1) {
        unsigned g = 0;
        #pragma unroll
        for (int p = 0; p < 16; p++) g += part[lane*16 + p];
        unsigned acc = g;
        #pragma unroll
        for (int off = 1; off < 32; off <<= 1) {
            unsigned vv = __shfl_up_sync(0xFFFFFFFFu, acc, off);
            if (lane >= off) acc += vv;
        }
        unsigned below = acc - g;
        if ((int)below < K && (int)(below + g) >= K) {
            unsigned run = below;
            int base = lane * 16;
            for (int p = 0; p < 16; ++p) {
                unsigned pc = part[base + p];
                if ((int)(run + pc) >= K) {
                    int bb = (base + p) * 4;
                    for (int b4 = 0; b4 < 4; ++b4) {
                        unsigned c = hist[bb + b4] + hist[HSTRIDE + bb + b4]
                                   + hist[2*HSTRIDE + bb + b4] + hist[3*HSTRIDE + bb + b4];
                        if ((int)(run + c) >= K) { s_Bl = bb + b4; s_rl = K - (int)run; break; }
                        run += c;
                    }
                    break;
                }
                run += pc;
            }
        }
    }
    __syncthreads();

    // ---- Phase 2: compact boundary-bin candidates ----
    {
        const unsigned Bh = (unsigned)s_Bh, Bl = (unsigned)s_Bl;
        #pragma unroll
        for (int e = 0; e < EPT; e++) {
            unsigned bin = key[e] >> BSHIFT;
            unsigned idx = (unsigned)(4*(tid + (e>>2)*THREADS) + (e&3));
            if (bin == Bh) { int p = atomicAdd(&s_cntH, 1); if (p < CAP) { listKH[p] = key[e]; listIH[p] = idx; } }
            if (bin == Bl) { int p = atomicAdd(&s_cntL, 1); if (p < CAP) { listKL[p] = key[e]; listIL[p] = idx; } }
        }
    }
    __syncthreads();

    const int nH = s_cntH, nL = s_cntL;
    const bool ovH = nH > CAP, ovL = nL > CAP;

    // ---- Phase 3: exact threshold + tie index cutoff (tiny O(n^2) rank) ----
    if (!ovH && tid < nH) {
        unsigned kj = listKH[tid], ij = listIH[tid];
        int rank = 0;
        for (int i = 0; i < nH; i++) {
            unsigned ki = listKH[i], ii = listIH[i];
            rank += (ki > kj) || (ki == kj && ii < ij);
        }
        if (rank == s_rh - 1) { s_Th = kj; s_Ih = ij; }
    }
    if (!ovL && tid < nL) {
        unsigned kj = listKL[tid], ij = listIL[tid];
        int rank = 0;
        for (int i = 0; i < nL; i++) {
            unsigned ki = listKL[i], ii = listIL[i];
            rank += (ki < kj) || (ki == kj && ii < ij);
        }
        if (rank == s_rl - 1) { s_Tl = kj; s_Il = ij; }
    }

    // ---- Rare exact fallback: block-uniform binary search ----
    if (ovH) {
        unsigned lo = 0, hi = 0xFFFFFFFFu;
        for (int it = 0; it < 32; ++it) {
            unsigned mid = lo + ((hi - lo) >> 1);
            if (tid == 0) s_red = 0;
            __syncthreads();
            int c = 0;
            #pragma unroll
            for (int e = 0; e < EPT; e++) c += (key[e] > mid);
            c = __reduce_add_sync(0xFFFFFFFFu, c);
            if (lane == 0) atomicAdd(&s_red, c);
            __syncthreads();
            int tot = s_red; __syncthreads();
            if (tot >= K) lo = mid + 1; else hi = mid;
        }
        unsigned Th = lo;
        if (tid == 0) s_red = 0;
        __syncthreads();
        { int c = 0;
          #pragma unroll
          for (int e = 0; e < EPT; e++) c += (key[e] > Th);
          c = __reduce_add_sync(0xFFFFFFFFu, c);
          if (lane == 0) atomicAdd(&s_red, c); }
        __syncthreads();
        int r = K - s_red; __syncthreads();
        unsigned lo2 = 0, hi2 = FDIM - 1;
        for (int it = 0; it < 13; ++it) {
            unsigned mid = lo2 + ((hi2 - lo2) >> 1);
            if (tid == 0) s_red = 0;
            __syncthreads();
            int c = 0;
            #pragma unroll
            for (int e = 0; e < EPT; e++) {
                unsigned idx = (unsigned)(4*(tid + (e>>2)*THREADS) + (e&3));
                c += (key[e] == Th && idx <= mid);
            }
            c = __reduce_add_sync(0xFFFFFFFFu, c);
            if (lane == 0) atomicAdd(&s_red, c);
            __syncthreads();
            int tot = s_red; __syncthreads();
            if (tot >= r) hi2 = mid; else lo2 = mid + 1;
        }
        if (tid == 0) { s_Th = Th; s_Ih = lo2; }
    }
    if (ovL) {
        unsigned lo = 0, hi = 0xFFFFFFFFu;
        for (int it = 0; it < 32; ++it) {
            unsigned mid = lo + ((hi - lo) >> 1);
            if (tid == 0) s_red = 0;
            __syncthreads();
            int c = 0;
            #pragma unroll
            for (int e = 0; e < EPT; e++) c += (key[e] <= mid);
            c = __reduce_add_sync(0xFFFFFFFFu, c);
            if (lane == 0) atomicAdd(&s_red, c);
            __syncthreads();
            int tot = s_red; __syncthreads();
            if (tot >= K) hi = mid; else lo = mid + 1;
        }
        unsigned Tl = lo;
        if (tid == 0) s_red = 0;
        __syncthreads();
        { int c = 0;
          #pragma unroll
          for (int e = 0; e < EPT; e++) c += (key[e] < Tl);
          c = __reduce_add_sync(0xFFFFFFFFu, c);
          if (lane == 0) atomicAdd(&s_red, c); }
        __syncthreads();
        int r = K - s_red; __syncthreads();
        unsigned lo2 = 0, hi2 = FDIM - 1;
        for (int it = 0; it < 13; ++it) {
            unsigned mid = lo2 + ((hi2 - lo2) >> 1);
            if (tid == 0) s_red = 0;
            __syncthreads();
            int c = 0;
            #pragma unroll
            for (int e = 0; e < EPT; e++) {
                unsigned idx = (unsigned)(4*(tid + (e>>2)*THREADS) + (e&3));
                c += (key[e] == Tl && idx <= mid);
            }
            c = __reduce_add_sync(0xFFFFFFFFu, c);
            if (lane == 0) atomicAdd(&s_red, c);
            __syncthreads();
            int tot = s_red; __syncthreads();
            if (tot >= r) hi2 = mid; else lo2 = mid + 1;
        }
        if (tid == 0) { s_Tl = Tl; s_Il = lo2; }
    }
    __syncthreads();

    // ---- Phase 4: masked write-out ----
    const unsigned Th = s_Th, Ih = s_Ih, Tl = s_Tl, Il = s_Il;
    #pragma unroll
    for (int k = 0; k < VPT; k++) {
        int v = tid + k * THREADS;
        float vals[4];
        #pragma unroll
        for (int c = 0; c < 4; c++) {
            unsigned kk  = key[4*k + c];
            unsigned idx = (unsigned)(4*v + c);
            bool z = (kk > Th) || (kk < Tl) ||
                     (kk == Th && idx <= Ih) ||
                     (kk == Tl && idx <= Il);
            vals[c] = z ? 0.0f : key2f(kk);
        }
        float4 o; o.x = vals[0]; o.y = vals[1]; o.z = vals[2]; o.w = vals[3];
        orow[v] = o;
    }
}

extern "C" void kernel_launch(void* const* d_in, const int* in_sizes, int n_in,
                              void* d_out, int out_size)
{
    const float* x = (const float*)d_in[0];
    const float* w = (const float*)d_in[1];
    const int* kp  = (n_in >= 3) ? (const int*)d_in[2] : nullptr;

    int Fdim = in_sizes[1];
    int B    = in_sizes[0] / Fdim;

    topk_mask_kernel<<<B, THREADS>>>(x, w, kp, (float*)d_out);
}